// round 3
// baseline (speedup 1.0000x reference)
#include <cuda_runtime.h>
#include <cstdint>

// Problem constants (fixed by the dataset)
#define MAXN 100000
#define MAXE 600000
#define DF   128            // feature dim (in == hid == 128)

// ---------------------------------------------------------------------------
// Scratch (no allocations allowed -> __device__ globals)
// ---------------------------------------------------------------------------
__device__ float g_z[(size_t)MAXN * DF];    // z_pre (linear output) of current layer
__device__ float g_agg[(size_t)MAXN * DF];  // aggregation accumulator / layer output
__device__ int   g_deg[MAXN];
__device__ float g_dinv[MAXN];

// ---------------------------------------------------------------------------
// Degree / normalization
// ---------------------------------------------------------------------------
__global__ void deg_init_kernel(int n) {
    int i = blockIdx.x * blockDim.x + threadIdx.x;
    if (i < n) g_deg[i] = 1;   // self-loop
}

__global__ void deg_count_kernel(const int* __restrict__ dst, int E) {
    int e = blockIdx.x * blockDim.x + threadIdx.x;
    if (e < E) atomicAdd(&g_deg[dst[e]], 1);
}

__global__ void dinv_kernel(int n) {
    int i = blockIdx.x * blockDim.x + threadIdx.x;
    if (i < n) g_dinv[i] = rsqrtf((float)g_deg[i]);
}

// ---------------------------------------------------------------------------
// Fused GEMM:  Zpre = act(A + preBias) @ W ;  Agg = Zpre * dinv^2 (self-loop)
//   ASRC = 0 : A comes from parameter pointer (external input x)
//   ASRC = 1 : A = g_agg (previous layer accumulator), in-place safe:
//              each block reads exactly the rows it later writes, and all
//              K-step loads complete before the epilogue stores.
//   PRERELU  : apply relu(a + preBias[k]) to A elements on load
// Tile: 128x128 output per block, K=128 in steps of 16, 256 threads, 8x8/thread
// ---------------------------------------------------------------------------
template<int ASRC, bool PRERELU>
__global__ void __launch_bounds__(256)
gemm_fused_kernel(const float* __restrict__ Aext,
                  const float* __restrict__ W,
                  const float* __restrict__ preBias,
                  int M)
{
    const int BM = 128, BK = 16;
    __shared__ float As[BK][BM];   // [k][m]
    __shared__ float Bs[BK][BM];   // [k][n]

    const float* A = (ASRC == 0) ? Aext : g_agg;

    int tid = threadIdx.x;
    int tx  = tid & 15;        // 0..15 -> col group (8 cols each)
    int ty  = tid >> 4;        // 0..15 -> row group (8 rows each)
    int rowBase = blockIdx.x * BM;

    float acc[8][8];
    #pragma unroll
    for (int i = 0; i < 8; i++)
        #pragma unroll
        for (int j = 0; j < 8; j++) acc[i][j] = 0.0f;

    for (int k0 = 0; k0 < DF; k0 += BK) {
        // --- load A tile: 128 rows x 16 k (512 float4, 2 per thread) ---
        #pragma unroll
        for (int it = 0; it < 2; ++it) {
            int q  = tid + it * 256;
            int r  = q >> 2;             // 0..127 row within tile
            int kk = (q & 3) << 2;       // 0,4,8,12
            int grow = rowBase + r;
            float4 v = make_float4(0.f, 0.f, 0.f, 0.f);
            if (grow < M)
                v = *(const float4*)(A + (size_t)grow * DF + k0 + kk);
            if (PRERELU) {
                float4 bb = *(const float4*)(preBias + k0 + kk);
                v.x = fmaxf(v.x + bb.x, 0.f);
                v.y = fmaxf(v.y + bb.y, 0.f);
                v.z = fmaxf(v.z + bb.z, 0.f);
                v.w = fmaxf(v.w + bb.w, 0.f);
            }
            As[kk + 0][r] = v.x;
            As[kk + 1][r] = v.y;
            As[kk + 2][r] = v.z;
            As[kk + 3][r] = v.w;
        }
        // --- load W tile: 16 k-rows x 128 cols (512 float4, 2 per thread) ---
        #pragma unroll
        for (int it = 0; it < 2; ++it) {
            int q = tid + it * 256;
            int r = q >> 5;              // 0..15
            int c = (q & 31) << 2;       // 0..124
            *(float4*)(&Bs[r][c]) = *(const float4*)(W + (size_t)(k0 + r) * DF + c);
        }
        __syncthreads();

        #pragma unroll
        for (int kk = 0; kk < BK; ++kk) {
            float ra[8], rb[8];
            #pragma unroll
            for (int i = 0; i < 8; i++) ra[i] = As[kk][ty * 8 + i];
            #pragma unroll
            for (int j = 0; j < 8; j++) rb[j] = Bs[kk][tx * 8 + j];
            #pragma unroll
            for (int i = 0; i < 8; i++)
                #pragma unroll
                for (int j = 0; j < 8; j++)
                    acc[i][j] = fmaf(ra[i], rb[j], acc[i][j]);
        }
        __syncthreads();
    }

    // --- epilogue: write Zpre and self-loop-initialized Agg ---
    #pragma unroll
    for (int i = 0; i < 8; i++) {
        int grow = rowBase + ty * 8 + i;
        if (grow >= M) continue;
        float di = g_dinv[grow];
        float d2 = di * di;
        size_t base = (size_t)grow * DF + tx * 8;
        #pragma unroll
        for (int j = 0; j < 8; j += 4) {
            float4 v = make_float4(acc[i][j], acc[i][j + 1], acc[i][j + 2], acc[i][j + 3]);
            *(float4*)(g_z + base + j) = v;
            float4 w = make_float4(v.x * d2, v.y * d2, v.z * d2, v.w * d2);
            *(float4*)(g_agg + base + j) = w;
        }
    }
}

// ---------------------------------------------------------------------------
// Edge scatter: one warp per edge.
//   g_agg[dst] += g_z[src] * (dinv[src]*dinv[dst]),  128 floats via
//   32 lanes x red.global.add.v4.f32 (vectorized L2 atomics, sm_90+)
// ---------------------------------------------------------------------------
__global__ void scatter_kernel(const int* __restrict__ src,
                               const int* __restrict__ dst,
                               int E)
{
    int warp = (blockIdx.x * blockDim.x + threadIdx.x) >> 5;
    int lane = threadIdx.x & 31;
    if (warp >= E) return;
    int s = __ldg(src + warp);
    int d = __ldg(dst + warp);
    float norm = g_dinv[s] * g_dinv[d];
    float4 v = *(const float4*)(g_z + (size_t)s * DF + lane * 4);
    float* p = g_agg + (size_t)d * DF + lane * 4;
    asm volatile("red.global.add.v4.f32 [%0], {%1, %2, %3, %4};"
                 :: "l"(p), "f"(v.x * norm), "f"(v.y * norm),
                    "f"(v.z * norm), "f"(v.w * norm)
                 : "memory");
}

// ---------------------------------------------------------------------------
// Edge decode: out[e] = sum_f (z[src]+b2)[f] * (z[dst]+b2)[f]
// One warp per edge; bias b2 fused here (z = g_agg, pre-bias).
// ---------------------------------------------------------------------------
__global__ void edge_dot_kernel(const int* __restrict__ src,
                                const int* __restrict__ dst,
                                const float* __restrict__ bias,
                                float* __restrict__ out,
                                int E)
{
    int warp = (blockIdx.x * blockDim.x + threadIdx.x) >> 5;
    int lane = threadIdx.x & 31;
    if (warp >= E) return;
    int s = __ldg(src + warp);
    int d = __ldg(dst + warp);
    float4 bb = *(const float4*)(bias + lane * 4);
    float4 a  = *(const float4*)(g_agg + (size_t)s * DF + lane * 4);
    float4 b  = *(const float4*)(g_agg + (size_t)d * DF + lane * 4);
    float p = (a.x + bb.x) * (b.x + bb.x)
            + (a.y + bb.y) * (b.y + bb.y)
            + (a.z + bb.z) * (b.z + bb.z)
            + (a.w + bb.w) * (b.w + bb.w);
    #pragma unroll
    for (int o = 16; o > 0; o >>= 1)
        p += __shfl_xor_sync(0xffffffffu, p, o);
    if (lane == 0) out[warp] = p;
}

// ---------------------------------------------------------------------------
// kernel_launch: full pipeline, all graph-capturable kernel launches
// Inputs (metadata order): x [N*128], edge_index [2*E], W1, b1, W2, b2
// ---------------------------------------------------------------------------
extern "C" void kernel_launch(void* const* d_in, const int* in_sizes, int n_in,
                              void* d_out, int out_size)
{
    const float* x  = (const float*)d_in[0];
    const int*   ei = (const int*)  d_in[1];
    const float* W1 = (const float*)d_in[2];
    const float* b1 = (const float*)d_in[3];
    const float* W2 = (const float*)d_in[4];
    const float* b2 = (const float*)d_in[5];

    int E = in_sizes[1] / 2;
    int N = in_sizes[0] / DF;
    if (N > MAXN) N = MAXN;
    if (E > MAXE) E = MAXE;

    const int* src = ei;
    const int* dst = ei + E;
    float* out = (float*)d_out;

    const int T = 256;

    // degrees & normalization
    deg_init_kernel<<<(N + T - 1) / T, T>>>(N);
    deg_count_kernel<<<(E + T - 1) / T, T>>>(dst, E);
    dinv_kernel<<<(N + T - 1) / T, T>>>(N);

    int gemm_blocks = (N + 127) / 128;
    // 8 warps per block -> 8 edges per block for warp-per-edge kernels
    int edge_blocks = (E + 7) / 8;

    // ---- Layer 1: z = GCNConv(x, W1, b1), relu deferred into GEMM2 load ----
    gemm_fused_kernel<0, false><<<gemm_blocks, T>>>(x, W1, nullptr, N);
    scatter_kernel<<<edge_blocks, T>>>(src, dst, E);
    // g_agg now = pre-bias layer-1 output (bias+relu applied on GEMM2 load)

    // ---- Layer 2: z2 = GCNConv(relu(agg1 + b1), W2, b2) ----
    gemm_fused_kernel<1, true><<<gemm_blocks, T>>>(nullptr, W2, b1, N);
    scatter_kernel<<<edge_blocks, T>>>(src, dst, E);
    // g_agg now = pre-bias layer-2 output (bias b2 fused into decode)

    // ---- Decode: per-edge dot of endpoint embeddings ----
    edge_dot_kernel<<<edge_blocks, T>>>(src, dst, b2, out, E);
}